// round 16
// baseline (speedup 1.0000x reference)
#include <cuda_runtime.h>
#include <math.h>
#include <stdint.h>

// Shapes (fixed by the problem)
#define BATCH 2
#define SEQ   2048
#define DM    1024
#define HEADS 16
#define DK    64
#define MROWS (BATCH * SEQ)          // 4096
#define LOG2E 1.44269504088896340736f

// Scratch: device globals (allocation-free rule). All hold tf32-rounded bits.
__device__ float g_X[MROWS * DM];                   // x, tf32 bits
__device__ float g_W[4 * DM * DM];                  // Wq|Wk|Wv|Wo, tf32 bits
__device__ float g_Q[BATCH * HEADS * SEQ * DK];     // [b,h,s,d] tf32 bits, pre-scaled 1/8
__device__ float g_K[BATCH * HEADS * SEQ * DK];     // tf32 bits
__device__ float g_V[BATCH * HEADS * SEQ * DK];     // tf32 bits
__device__ float g_ATT[MROWS * DM];                 // [b,s, h*64+d] tf32 bits

__device__ __forceinline__ float to_tf32(float x) {
    float y;
    asm("cvt.rna.tf32.f32 %0, %1;" : "=f"(y) : "f"(x));
    return y;
}
__device__ __forceinline__ float exp2a(float x) {
    float y;
    asm("ex2.approx.f32 %0, %1;" : "=f"(y) : "f"(x));
    return y;
}
__device__ __forceinline__ void mma_tf32(float* c, const uint32_t* a, const uint32_t* b) {
    asm volatile(
        "mma.sync.aligned.m16n8k8.row.col.f32.tf32.tf32.f32 "
        "{%0,%1,%2,%3}, {%4,%5,%6,%7}, {%8,%9}, {%0,%1,%2,%3};"
        : "+f"(c[0]), "+f"(c[1]), "+f"(c[2]), "+f"(c[3])
        : "r"(a[0]), "r"(a[1]), "r"(a[2]), "r"(a[3]), "r"(b[0]), "r"(b[1]));
}
__device__ __forceinline__ uint32_t smem_u32(const void* p) {
    uint32_t a;
    asm("{ .reg .u64 t; cvta.to.shared.u64 t, %1; cvt.u32.u64 %0, t; }"
        : "=r"(a) : "l"(p));
    return a;
}
__device__ __forceinline__ void cp16(uint32_t dst, const float* src) {
    asm volatile("cp.async.cg.shared.global [%0], [%1], 16;" :: "r"(dst), "l"(src));
}
__device__ __forceinline__ void cp_commit() { asm volatile("cp.async.commit_group;" ::: "memory"); }
__device__ __forceinline__ void cp_wait0()  { asm volatile("cp.async.wait_group 0;" ::: "memory"); }
__device__ __forceinline__ void cp_wait1()  { asm volatile("cp.async.wait_group 1;" ::: "memory"); }

// ---------------------------------------------------------------------------
// tf32 pre-convert: x -> g_X, {Wq,Wk,Wv,Wo} -> g_W (RNA rounding once).
// ---------------------------------------------------------------------------
__global__ __launch_bounds__(256) void convert_tf32(
    const float* __restrict__ x,
    const float* __restrict__ wq, const float* __restrict__ wk,
    const float* __restrict__ wv, const float* __restrict__ wo)
{
    const size_t idx = (size_t)blockIdx.x * 256 + threadIdx.x;   // float4 index
    const float* src;
    float* dst;
    size_t off;
    if (idx < (1u << 20)) {                       // x: 4M floats = 1M float4
        src = x; dst = g_X; off = idx;
    } else {
        const size_t r = idx - (1u << 20);
        const size_t w = r >> 18;                 // each W: 256K float4
        off = r & ((1u << 18) - 1);
        src = (w == 0) ? wq : (w == 1) ? wk : (w == 2) ? wv : wo;
        dst = g_W + (w << 20);
    }
    float4 v = ((const float4*)src)[off];
    v.x = to_tf32(v.x); v.y = to_tf32(v.y);
    v.z = to_tf32(v.z); v.w = to_tf32(v.w);
    ((float4*)dst)[off] = v;
}

// ---------------------------------------------------------------------------
// tf32 GEMM: C[4096,1024] = A @ W + bias; inputs pre-converted tf32 bits.
// CTA tile 128x128, 256 threads = 2(m) x 4(n) warps; warp tile 64x32.
// 3-stage cp.async pipeline, K-chunk 32 (4 q-steps, 64 MMAs per barrier).
// ---------------------------------------------------------------------------
#define AST 36               // A floats per m-row (144B, 16B aligned)
#define BST 136              // B floats per k-row (544B, 16B aligned)
#define A_F (128 * AST)      // 4608 floats
#define B_F (32 * BST)       // 4352 floats
#define STG_F (A_F + B_F)    // 8960 floats (35840B)
#define NSTG 3
#define OFF_A 128
#define GEMM_SMEM ((OFF_A + NSTG * STG_F) * 4)     // 108032 bytes

__global__ __launch_bounds__(256, 2) void gemm_mma(
    const float* __restrict__ b0, const float* __restrict__ b1,
    const float* __restrict__ b2, float* __restrict__ Cout, int isOut)
{
    extern __shared__ float smem[];

    const int z = blockIdx.z;
    const float* A    = isOut ? g_ATT : g_X;
    const float* W    = isOut ? (g_W + 3u * (1u << 20)) : (g_W + (size_t)z * (1u << 20));
    const float* bias = isOut ? b0 : (z == 0) ? b0 : (z == 1) ? b1 : b2;

    const int tid  = threadIdx.x;
    const int wid  = tid >> 5;
    const int lane = tid & 31;
    const int wm   = wid >> 2;
    const int wn   = wid & 3;
    const int g    = lane >> 2;
    const int tig  = lane & 3;

    const int bm = blockIdx.y * 128;
    const int bn = blockIdx.x * 128;

    if (tid < 128) smem[tid] = bias[bn + tid];

    const uint32_t sb = smem_u32(smem);
    const int arow = tid >> 3, ac4 = tid & 7;
    const int brow = tid >> 5, bn4 = tid & 31;

    auto issue = [&](int c, int s) {
        const int k0 = c * 32;
        const uint32_t ab = sb + (OFF_A + s * STG_F) * 4;
        const uint32_t bb = ab + A_F * 4;
        #pragma unroll
        for (int j = 0; j < 4; j++) {
            cp16(ab + ((arow + j * 32) * AST + ac4 * 4) * 4,
                 &A[(size_t)(bm + arow + j * 32) * DM + k0 + ac4 * 4]);
            cp16(bb + ((brow + j * 8) * BST + bn4 * 4) * 4,
                 &W[(size_t)(k0 + brow + j * 8) * DM + bn + bn4 * 4]);
        }
        cp_commit();
    };

    issue(0, 0); issue(1, 1);

    float c[4][4][4] = {};

    int stg = 2;
    #pragma unroll 1
    for (int i = 0; i < 32; i++) {
        cp_wait1();
        __syncthreads();
        if (i < 30) {
            issue(i + 2, stg);
            stg = (stg == 2) ? 0 : stg + 1;
        }

        const int cs = (i % 3);
        const float* As = smem + OFF_A + cs * STG_F;
        const float* Bs = As + A_F;
        #pragma unroll
        for (int q = 0; q < 4; q++) {
            uint32_t af[4][4], bf[4][2];
            #pragma unroll
            for (int mf = 0; mf < 4; mf++) {
                const uint32_t* base = (const uint32_t*)&As[(wm * 64 + mf * 16 + g) * AST + q * 8 + tig];
                af[mf][0] = base[0];
                af[mf][1] = base[8 * AST];
                af[mf][2] = base[4];
                af[mf][3] = base[8 * AST + 4];
            }
            #pragma unroll
            for (int nf = 0; nf < 4; nf++) {
                const uint32_t* base = (const uint32_t*)&Bs[(q * 8 + tig) * BST + wn * 32 + nf * 8 + g];
                bf[nf][0] = base[0];
                bf[nf][1] = base[4 * BST];
            }
            #pragma unroll
            for (int mf = 0; mf < 4; mf++)
                #pragma unroll
                for (int nf = 0; nf < 4; nf++)
                    mma_tf32(c[mf][nf], af[mf], bf[nf]);
        }
    }

    float* O = isOut ? Cout : (z == 0) ? g_Q : (z == 1) ? g_K : g_V;
    const float qsc = (!isOut && z == 0) ? 0.125f : 1.0f;

    #pragma unroll
    for (int mf = 0; mf < 4; mf++) {
        const int row = bm + wm * 64 + mf * 16 + g;
        #pragma unroll
        for (int nf = 0; nf < 4; nf++) {
            const int colt = wn * 32 + nf * 8 + tig * 2;
            const float bx = smem[colt];
            const float by = smem[colt + 1];
            size_t base0, base1;
            if (isOut) {
                base0 = (size_t)row * DM + bn + colt;
                base1 = (size_t)(row + 8) * DM + bn + colt;
            } else {
                const int col = bn + colt;
                const int h = col >> 6, d0 = col & 63;
                const int b_ = row >> 11;
                const int s0 = row & 2047;
                base0 = ((size_t)(b_ * HEADS + h) * SEQ + s0) * DK + d0;
                base1 = base0 + 8 * DK;
            }
            float2 v0 = { c[mf][nf][0] + bx, c[mf][nf][1] + by };
            float2 v1 = { c[mf][nf][2] + bx, c[mf][nf][3] + by };
            if (!isOut) {
                v0.x = to_tf32(v0.x * qsc); v0.y = to_tf32(v0.y * qsc);
                v1.x = to_tf32(v1.x * qsc); v1.y = to_tf32(v1.y * qsc);
            }
            *(float2*)&O[base0] = v0;
            *(float2*)&O[base1] = v1;
        }
    }
}

// ---------------------------------------------------------------------------
// Flash attention on mma.sync tf32.
// CTA: 256 threads (8 warps), 128 queries of one (b,h); warp = 16 query rows.
// All 8 warps share the K/V smem tiles (KV traffic halved vs 4-warp CTA).
// KV tiles of 64 keys, double-buffered cp.async.
// ---------------------------------------------------------------------------
#define KSTR 68
#define VSTR 72
#define PSTR 68
#define KBUF (64 * KSTR)
#define VBUF (64 * VSTR)
#define PBUF (16 * PSTR)
#define NWARP 8
#define FLASH_SMEM ((2 * KBUF + 2 * VBUF + NWARP * PBUF) * 4)   // 106496 bytes

__global__ __launch_bounds__(256, 2) void flash_mma()
{
    extern __shared__ float fs[];
    const int tid  = threadIdx.x;
    const int wid  = tid >> 5;
    const int lane = tid & 31;
    const int g    = lane >> 2;
    const int tig  = lane & 3;

    const int bh = blockIdx.y;
    const int qb = blockIdx.x * 128;

    const float* Qg = g_Q + (size_t)bh * SEQ * DK;
    const float* Kg = g_K + (size_t)bh * SEQ * DK;
    const float* Vg = g_V + (size_t)bh * SEQ * DK;

    float* Pw = fs + 2 * KBUF + 2 * VBUF + wid * PBUF;
    const uint32_t sb = smem_u32(fs);

    // Q fragments: rows qb + wid*16 + {g, g+8}, persistent in registers
    uint32_t qa[8][4];
    {
        const int r0 = qb + wid * 16 + g;
        #pragma unroll
        for (int ks = 0; ks < 8; ks++) {
            qa[ks][0] = __float_as_uint(Qg[(size_t)r0 * DK + ks * 8 + tig]);
            qa[ks][1] = __float_as_uint(Qg[(size_t)(r0 + 8) * DK + ks * 8 + tig]);
            qa[ks][2] = __float_as_uint(Qg[(size_t)r0 * DK + ks * 8 + tig + 4]);
            qa[ks][3] = __float_as_uint(Qg[(size_t)(r0 + 8) * DK + ks * 8 + tig + 4]);
        }
    }

    float o[8][4] = {};
    float mr0 = -INFINITY, mr1 = -INFINITY;
    float l0 = 0.f, l1 = 0.f;

    // tile loader: K 1024 float4 + V 1024 float4, 4+4 per thread (256 thr)
    auto load_tile = [&](int t) {
        const int buf = t & 1;
        const float* Ksrc = Kg + (size_t)t * 64 * DK;
        const float* Vsrc = Vg + (size_t)t * 64 * DK;
        const uint32_t kd = sb + buf * KBUF * 4;
        const uint32_t vd = sb + (2 * KBUF + buf * VBUF) * 4;
        #pragma unroll
        for (int i = 0; i < 4; i++) {
            int idx = tid + i * 256;
            int row = idx >> 4, c4 = idx & 15;
            cp16(kd + (row * KSTR + c4 * 4) * 4, Ksrc + row * 64 + c4 * 4);
        }
        #pragma unroll
        for (int i = 0; i < 4; i++) {
            int idx = tid + i * 256;
            int row = idx >> 4, c4 = idx & 15;
            cp16(vd + (row * VSTR + c4 * 4) * 4, Vsrc + row * 64 + c4 * 4);
        }
    };

    load_tile(0);
    cp_commit();

    #pragma unroll 1
    for (int t = 0; t < SEQ / 64; t++) {
        cp_wait0();
        __syncthreads();
        if (t + 1 < SEQ / 64) {
            load_tile(t + 1);
            cp_commit();
        }

        const float* Kt = fs + (t & 1) * KBUF;
        const float* Vt = fs + 2 * KBUF + (t & 1) * VBUF;

        // ---- S = Q K^T (Q pre-scaled by 1/8)
        float s[8][4] = {};
        #pragma unroll
        for (int ks = 0; ks < 8; ks++) {
            #pragma unroll
            for (int nt = 0; nt < 8; nt++) {
                const uint32_t* bp = (const uint32_t*)&Kt[(nt * 8 + g) * KSTR + ks * 8 + tig];
                uint32_t b[2] = { bp[0], bp[4] };
                mma_tf32(s[nt], qa[ks], b);
            }
        }

        // ---- online softmax
        float m0 = -INFINITY, m1 = -INFINITY;
        #pragma unroll
        for (int nt = 0; nt < 8; nt++) {
            m0 = fmaxf(m0, fmaxf(s[nt][0], s[nt][1]));
            m1 = fmaxf(m1, fmaxf(s[nt][2], s[nt][3]));
        }
        m0 = fmaxf(m0, __shfl_xor_sync(0xffffffffu, m0, 1));
        m0 = fmaxf(m0, __shfl_xor_sync(0xffffffffu, m0, 2));
        m1 = fmaxf(m1, __shfl_xor_sync(0xffffffffu, m1, 1));
        m1 = fmaxf(m1, __shfl_xor_sync(0xffffffffu, m1, 2));

        const float nm0 = fmaxf(mr0, m0), nm1 = fmaxf(mr1, m1);
        const float corr0 = exp2a((mr0 - nm0) * LOG2E);
        const float corr1 = exp2a((mr1 - nm1) * LOG2E);
        mr0 = nm0; mr1 = nm1;
        const float c0 = nm0 * LOG2E, c1 = nm1 * LOG2E;

        float t0 = 0.f, t1 = 0.f;
        #pragma unroll
        for (int nt = 0; nt < 8; nt++) {
            float p0 = to_tf32(exp2a(fmaf(s[nt][0], LOG2E, -c0)));
            float p1 = to_tf32(exp2a(fmaf(s[nt][1], LOG2E, -c0)));
            float p2 = to_tf32(exp2a(fmaf(s[nt][2], LOG2E, -c1)));
            float p3 = to_tf32(exp2a(fmaf(s[nt][3], LOG2E, -c1)));
            s[nt][0] = p0; s[nt][1] = p1; s[nt][2] = p2; s[nt][3] = p3;
            t0 += p0 + p1;
            t1 += p2 + p3;
        }
        t0 += __shfl_xor_sync(0xffffffffu, t0, 1);
        t0 += __shfl_xor_sync(0xffffffffu, t0, 2);
        t1 += __shfl_xor_sync(0xffffffffu, t1, 1);
        t1 += __shfl_xor_sync(0xffffffffu, t1, 2);
        l0 = l0 * corr0 + t0;
        l1 = l1 * corr1 + t1;

        #pragma unroll
        for (int nd = 0; nd < 8; nd++) {
            o[nd][0] *= corr0; o[nd][1] *= corr0;
            o[nd][2] *= corr1; o[nd][3] *= corr1;
        }

        // ---- P: C-frag -> A-frag via per-warp smem
        #pragma unroll
        for (int nt = 0; nt < 8; nt++) {
            *(float2*)&Pw[g * PSTR + nt * 8 + 2 * tig]       = make_float2(s[nt][0], s[nt][1]);
            *(float2*)&Pw[(g + 8) * PSTR + nt * 8 + 2 * tig] = make_float2(s[nt][2], s[nt][3]);
        }
        __syncwarp();

        // ---- O += P V
        #pragma unroll
        for (int ks = 0; ks < 8; ks++) {
            uint32_t a[4];
            a[0] = __float_as_uint(Pw[g * PSTR + ks * 8 + tig]);
            a[1] = __float_as_uint(Pw[(g + 8) * PSTR + ks * 8 + tig]);
            a[2] = __float_as_uint(Pw[g * PSTR + ks * 8 + tig + 4]);
            a[3] = __float_as_uint(Pw[(g + 8) * PSTR + ks * 8 + tig + 4]);
            #pragma unroll
            for (int nd = 0; nd < 8; nd++) {
                const uint32_t* bp0 = (const uint32_t*)&Vt[(ks * 8 + tig) * VSTR + nd * 8 + g];
                const uint32_t* bp1 = (const uint32_t*)&Vt[(ks * 8 + tig + 4) * VSTR + nd * 8 + g];
                uint32_t b[2] = { bp0[0], bp1[0] };
                mma_tf32(o[nd], a, b);
            }
        }
    }

    // ---- epilogue: normalize, tf32-round, store to g_ATT [b,s, h*64+d]
    const float i0 = 1.0f / l0;
    const float i1 = 1.0f / l1;
    const int b_ = bh >> 4;
    const int h  = bh & 15;
    const int s0 = qb + wid * 16 + g;
    float* O0 = &g_ATT[((size_t)b_ * SEQ + s0) * DM + h * DK];
    float* O1 = &g_ATT[((size_t)b_ * SEQ + s0 + 8) * DM + h * DK];
    #pragma unroll
    for (int nd = 0; nd < 8; nd++) {
        *(float2*)&O0[nd * 8 + 2 * tig] =
            make_float2(to_tf32(o[nd][0] * i0), to_tf32(o[nd][1] * i0));
        *(float2*)&O1[nd * 8 + 2 * tig] =
            make_float2(to_tf32(o[nd][2] * i1), to_tf32(o[nd][3] * i1));
    }
}

// ---------------------------------------------------------------------------
extern "C" void kernel_launch(void* const* d_in, const int* in_sizes, int n_in,
                              void* d_out, int out_size)
{
    const float* x  = (const float*)d_in[0];
    const float* Wq = (const float*)d_in[1];
    const float* bq = (const float*)d_in[2];
    const float* Wk = (const float*)d_in[3];
    const float* bk = (const float*)d_in[4];
    const float* Wv = (const float*)d_in[5];
    const float* bv = (const float*)d_in[6];
    const float* Wo = (const float*)d_in[7];
    const float* bo = (const float*)d_in[8];
    float* out = (float*)d_out;

    cudaFuncSetAttribute(gemm_mma, cudaFuncAttributeMaxDynamicSharedMemorySize,
                         GEMM_SMEM);
    cudaFuncSetAttribute(flash_mma, cudaFuncAttributeMaxDynamicSharedMemorySize,
                         FLASH_SMEM);

    // 0) tf32 pre-convert: x -> g_X, W's -> g_W
    convert_tf32<<<8192, 256>>>(x, Wq, Wk, Wv, Wo);

    // 1) QKV projections -> split-head scratch (tf32 bits, Q pre-scaled 1/8)
    dim3 gq(DM / 128, MROWS / 128, 3);
    gemm_mma<<<gq, 256, GEMM_SMEM>>>(bq, bk, bv, nullptr, 0);

    // 2) Flash attention (tensor-core) -> g_ATT (tf32 bits)
    dim3 gf(SEQ / 128, BATCH * HEADS, 1);
    flash_mma<<<gf, 256, FLASH_SMEM>>>();

    // 3) Output projection, reads g_ATT/g_W
    dim3 go(DM / 128, MROWS / 128, 1);
    gemm_mma<<<go, 256, GEMM_SMEM>>>(bo, nullptr, nullptr, out, 1);
}